// round 10
// baseline (speedup 1.0000x reference)
#include <cuda_runtime.h>

#define BATCH 8
#define SEQ   1024
#define EMB   512
#define HEADS 8
#define DK    64
#define NW    8
#define BH    (BATCH*HEADS)
#define TM    128          // rows per CTA (4 warps x m=32)
#define TJ    64           // j-tile
#define NT    (SEQ/TJ)     // 16 tiles
#define VSTR  72           // V smem row stride (floats): bank=(8*tig+g+8*nb)%32 -> conflict-free

// Precomputed tables (device globals; allocation is forbidden)
__device__ float2 g_cs[BH*NW*SEQ];          // (cos, sin) per (bh, wire, s)
__device__ float  g_vh[(size_t)BH*SEQ*DK];  // V rounded to tf32 (fp32 bit layout)

static __device__ __forceinline__ unsigned cvt_tf32(float f){
    unsigned r; asm("cvt.rna.tf32.f32 %0, %1;" : "=r"(r) : "f"(f)); return r;
}
static __device__ __forceinline__ unsigned sptr(const void* p){
    return (unsigned)__cvta_generic_to_shared(p);
}
static __device__ __forceinline__ void cp16(unsigned dst, const void* src){
    asm volatile("cp.async.cg.shared.global [%0], [%1], 16;" :: "r"(dst), "l"(src) : "memory");
}

// Pass 1a: cos/sin table. One thread per (bh, w, s): 512K threads.
__global__ void precompute_cs(const float* __restrict__ x){
    int idx = blockIdx.x*blockDim.x + threadIdx.x;      // (bh*NW + w)*SEQ + s
    int s   = idx & (SEQ-1);
    int bhw = idx >> 10;
    int w   = bhw & (NW-1);
    int bh  = bhw >> 3;
    int b = bh >> 3, h = bh & 7;
    float v = x[((size_t)(b*SEQ + s))*EMB + h*DK + w];
    float sn, cs;
    sincosf(0.5f*v, &sn, &cs);
    g_cs[idx] = make_float2(cs, sn);
}

// Pass 1b: tf32-rounded V. One thread per float4: 1M threads.
__global__ void precompute_vh(const float* __restrict__ x){
    int idx = blockIdx.x*blockDim.x + threadIdx.x;      // (bh*SEQ+s)*16 + d4
    int d4  = idx & 15;
    int bhs = idx >> 4;
    int s   = bhs & (SEQ-1);
    int bh  = bhs >> 10;
    int b = bh >> 3, h = bh & 7;
    float4 v = ((const float4*)x)[((size_t)(b*SEQ + s))*(EMB/4) + h*(DK/4) + d4];
    float4 o;
    o.x = __uint_as_float(cvt_tf32(v.x));
    o.y = __uint_as_float(cvt_tf32(v.y));
    o.z = __uint_as_float(cvt_tf32(v.z));
    o.w = __uint_as_float(cvt_tf32(v.w));
    ((float4*)g_vh)[idx] = o;
}

// Pass 2: fused score -> exp -> tensor-core PV (tf32 hi) -> normalize.
// 4 warps; warp w owns rows [w*32, w*32+32) as TWO m16 MMA blocks sharing B
// fragments. Thread (g,tig): rows {g, g+8, g+16, g+24}, cols j=8kb+{tig,tig+4}.
// Double-buffered cp.async staging of (cos,sin) and V tiles.
__global__ void __launch_bounds__(128, 3)
qk_attn6(float* __restrict__ out){
    __shared__ __align__(16) float2 sCS[2][NW][TJ];    // (cos, sin)
    __shared__ __align__(16) float  sVh[2][TJ*VSTR];

    const int bh = blockIdx.y, b = bh >> 3, h = bh & 7;
    const int tid = threadIdx.x;
    const int w   = tid >> 5;
    const int lane = tid & 31;
    const int g   = lane >> 2, tig = lane & 3;
    const int ibase = blockIdx.x*TM + w*32 + g;   // row r -> ibase + 8r

    // i-side wire values for the thread's 4 rows
    float ci[4][NW], si[4][NW];
#pragma unroll
    for (int r = 0; r < 4; ++r)
#pragma unroll
        for (int q = 0; q < NW; ++q){
            float2 a = g_cs[(bh*NW + q)*SEQ + ibase + 8*r];
            ci[r][q] = a.x; si[r][q] = a.y;
        }

    float acc0[8][4], acc1[8][4];   // block0: rows g,g+8; block1: rows g+16,g+24
#pragma unroll
    for (int nb = 0; nb < 8; ++nb)
#pragma unroll
        for (int k = 0; k < 4; ++k){ acc0[nb][k] = 0.f; acc1[nb][k] = 0.f; }
    float ps[4] = {0.f, 0.f, 0.f, 0.f};

    // per-thread staging indices (fixed across tiles)
    const int csW  = tid >> 4;          // wire 0..7
    const int csF4 = (tid & 15)*2;      // float4 index within wire row
#define PREFETCH(T, BUF) do{                                                      \
        int jp_ = (T)*TJ;                                                         \
        const float4* gcs_ = (const float4*)&g_cs[(bh*NW + csW)*SEQ + jp_];       \
        cp16(sptr(&sCS[BUF][csW][csF4*2]),     gcs_ + csF4);                      \
        cp16(sptr(&sCS[BUF][csW][csF4*2 + 2]), gcs_ + csF4 + 1);                  \
        _Pragma("unroll")                                                         \
        for (int r_ = 0; r_ < 8; ++r_){                                           \
            int l_ = tid + r_*128;                                                \
            int row_ = l_ >> 4, c4_ = l_ & 15;                                    \
            cp16(sptr(&sVh[BUF][row_*VSTR + c4_*4]),                              \
                 ((const float4*)g_vh) + ((size_t)bh*SEQ + jp_ + row_)*(DK/4) + c4_); \
        }                                                                         \
        asm volatile("cp.async.commit_group;" ::: "memory");                      \
    }while(0)

    PREFETCH(0, 0);

    for (int jt = 0; jt < NT; ++jt){
        const int buf = jt & 1;
        if (jt + 1 < NT){
            PREFETCH(jt + 1, buf ^ 1);
            asm volatile("cp.async.wait_group 1;" ::: "memory");
        } else {
            asm volatile("cp.async.wait_group 0;" ::: "memory");
        }
        __syncthreads();

#pragma unroll
        for (int kb = 0; kb < 8; ++kb){
            const int ja = kb*8 + tig, jb = ja + 4;
            // 8 score products: 4 rows x 2 cols (scalar)
            float pA[4], pB[4];
            {
                float2 t = sCS[buf][0][ja], u = sCS[buf][0][jb];
#pragma unroll
                for (int r = 0; r < 4; ++r){
                    pA[r] = ci[r][0]*t.x + si[r][0]*t.y;
                    pB[r] = ci[r][0]*u.x + si[r][0]*u.y;
                }
            }
#pragma unroll
            for (int q = 1; q < NW; ++q){
                float2 t = sCS[buf][q][ja], u = sCS[buf][q][jb];
#pragma unroll
                for (int r = 0; r < 4; ++r){
                    pA[r] *= ci[r][q]*t.x + si[r][q]*t.y;
                    pB[r] *= ci[r][q]*u.x + si[r][q]*u.y;
                }
            }
            // diagonal score = 1 is the softmax max -> raw exp is safe
            float eA[4], eB[4];
#pragma unroll
            for (int r = 0; r < 4; ++r){
                eA[r] = __expf(fabsf(pA[r]));
                eB[r] = __expf(fabsf(pB[r]));
                ps[r] += eA[r] + eB[r];
            }
            // tf32 A-fragments (hi only; V already tf32)
            unsigned a00 = cvt_tf32(eA[0]), a01 = cvt_tf32(eA[1]);
            unsigned a02 = cvt_tf32(eB[0]), a03 = cvt_tf32(eB[1]);
            unsigned a10 = cvt_tf32(eA[2]), a11 = cvt_tf32(eA[3]);
            unsigned a12 = cvt_tf32(eB[2]), a13 = cvt_tf32(eB[3]);

            const float* vA = &sVh[buf][ja*VSTR + g];
            const float* vB = &sVh[buf][jb*VSTR + g];
#pragma unroll
            for (int nb = 0; nb < 8; ++nb){
                unsigned b0 = __float_as_uint(vA[nb*8]);
                unsigned b1 = __float_as_uint(vB[nb*8]);
                asm volatile(
                    "mma.sync.aligned.m16n8k8.row.col.f32.tf32.tf32.f32 "
                    "{%0,%1,%2,%3}, {%4,%5,%6,%7}, {%8,%9}, {%0,%1,%2,%3};"
                    : "+f"(acc0[nb][0]), "+f"(acc0[nb][1]),
                      "+f"(acc0[nb][2]), "+f"(acc0[nb][3])
                    : "r"(a00), "r"(a01), "r"(a02), "r"(a03), "r"(b0), "r"(b1));
                asm volatile(
                    "mma.sync.aligned.m16n8k8.row.col.f32.tf32.tf32.f32 "
                    "{%0,%1,%2,%3}, {%4,%5,%6,%7}, {%8,%9}, {%0,%1,%2,%3};"
                    : "+f"(acc1[nb][0]), "+f"(acc1[nb][1]),
                      "+f"(acc1[nb][2]), "+f"(acc1[nb][3])
                    : "r"(a10), "r"(a11), "r"(a12), "r"(a13), "r"(b0), "r"(b1));
            }
        }
        __syncthreads();
    }

    // row sums: reduce over the 4 tig lanes (xor 1, 2)
#pragma unroll
    for (int r = 0; r < 4; ++r){
        ps[r] += __shfl_xor_sync(0xffffffffu, ps[r], 1);
        ps[r] += __shfl_xor_sync(0xffffffffu, ps[r], 2);
    }
    const float inv0 = 1.0f/ps[0], inv1 = 1.0f/ps[1];
    const float inv2 = 1.0f/ps[2], inv3 = 1.0f/ps[3];

#pragma unroll
    for (int nb = 0; nb < 8; ++nb){
        size_t col = h*DK + nb*8 + 2*tig;
        size_t o0 = ((size_t)(b*SEQ + ibase +  0))*EMB + col;
        size_t o1 = ((size_t)(b*SEQ + ibase +  8))*EMB + col;
        size_t o2 = ((size_t)(b*SEQ + ibase + 16))*EMB + col;
        size_t o3 = ((size_t)(b*SEQ + ibase + 24))*EMB + col;
        *(float2*)&out[o0] = make_float2(acc0[nb][0]*inv0, acc0[nb][1]*inv0);
        *(float2*)&out[o1] = make_float2(acc0[nb][2]*inv1, acc0[nb][3]*inv1);
        *(float2*)&out[o2] = make_float2(acc1[nb][0]*inv2, acc1[nb][1]*inv2);
        *(float2*)&out[o3] = make_float2(acc1[nb][2]*inv3, acc1[nb][3]*inv3);
    }
#undef PREFETCH
}

extern "C" void kernel_launch(void* const* d_in, const int* in_sizes, int n_in,
                              void* d_out, int out_size){
    const float* x = (const float*)d_in[0];
    float* out = (float*)d_out;
    precompute_cs<<<(BH*NW*SEQ)/256, 256>>>(x);
    precompute_vh<<<((size_t)BH*SEQ*16)/256, 256>>>(x);
    dim3 grid(SEQ/TM, BH);
    qk_attn6<<<grid, 128>>>(out);
}

// round 11
// speedup vs baseline: 1.5360x; 1.5360x over previous
#include <cuda_runtime.h>

#define BATCH 8
#define SEQ   1024
#define EMB   512
#define HEADS 8
#define DK    64
#define NW    8
#define NP    4            // wire pairs
#define BH    (BATCH*HEADS)
#define TM    128          // rows per CTA (4 warps x m=32)
#define TJ    64           // j-tile
#define NT    (SEQ/TJ)
#define VSTR  72           // V smem row stride: bank=(8*tig+g+8*nb)%32 conflict-free

// Precomputed tables (device globals; allocation is forbidden)
__device__ float4 g_uh[BH*NP*SEQ];          // pair u-vectors, tf32 hi
__device__ float4 g_ul[BH*NP*SEQ];          // tf32 lo residual
__device__ float  g_vh[(size_t)BH*SEQ*DK];  // V rounded to tf32

static __device__ __forceinline__ unsigned cvt_tf32(float f){
    unsigned r; asm("cvt.rna.tf32.f32 %0, %1;" : "=r"(r) : "f"(f)); return r;
}

// QK: m16n8k4, D = A*B + 0
#define MMA_K4_Z(D, A0, A1, B)                                              \
    asm volatile("mma.sync.aligned.m16n8k4.row.col.f32.tf32.tf32.f32 "      \
        "{%0,%1,%2,%3}, {%4,%5}, {%6}, {%7,%7,%7,%7};"                      \
        : "=f"((D)[0]), "=f"((D)[1]), "=f"((D)[2]), "=f"((D)[3])            \
        : "r"(A0), "r"(A1), "r"(B), "f"(0.f))
// QK: m16n8k4, D += A*B
#define MMA_K4_ACC(D, A0, A1, B)                                            \
    asm volatile("mma.sync.aligned.m16n8k4.row.col.f32.tf32.tf32.f32 "      \
        "{%0,%1,%2,%3}, {%4,%5}, {%6}, {%0,%1,%2,%3};"                      \
        : "+f"((D)[0]), "+f"((D)[1]), "+f"((D)[2]), "+f"((D)[3])            \
        : "r"(A0), "r"(A1), "r"(B))
// PV: m16n8k8, D += A*B
#define MMA_K8_ACC(D, A0, A1, A2, A3, B0, B1)                               \
    asm volatile("mma.sync.aligned.m16n8k8.row.col.f32.tf32.tf32.f32 "      \
        "{%0,%1,%2,%3}, {%4,%5,%6,%7}, {%8,%9}, {%0,%1,%2,%3};"             \
        : "+f"((D)[0]), "+f"((D)[1]), "+f"((D)[2]), "+f"((D)[3])            \
        : "r"(A0), "r"(A1), "r"(A2), "r"(A3), "r"(B0), "r"(B1))

// Pass 1a: pair u-vectors. One thread per (bh, pair, s): 256K threads.
// u = (ca*cb, ca*sb, sa*cb, sa*sb); dot(u_i,u_j) = cos((xa_i-xa_j)/2)*cos((xb_i-xb_j)/2)
__global__ void precompute_u(const float* __restrict__ x){
    int idx = blockIdx.x*blockDim.x + threadIdx.x;   // (bh*NP + p)*SEQ + s
    int s   = idx & (SEQ-1);
    int bhp = idx >> 10;
    int p   = bhp & (NP-1);
    int bh  = bhp >> 2;
    int b = bh >> 3, h = bh & 7;
    float2 xv = *(const float2*)&x[((size_t)(b*SEQ+s))*EMB + h*DK + 2*p];
    float sa, ca, sb, cb;
    sincosf(0.5f*xv.x, &sa, &ca);
    sincosf(0.5f*xv.y, &sb, &cb);
    float u0 = ca*cb, u1 = ca*sb, u2 = sa*cb, u3 = sa*sb;
    float h0 = __uint_as_float(cvt_tf32(u0));
    float h1 = __uint_as_float(cvt_tf32(u1));
    float h2 = __uint_as_float(cvt_tf32(u2));
    float h3 = __uint_as_float(cvt_tf32(u3));
    g_uh[idx] = make_float4(h0, h1, h2, h3);
    g_ul[idx] = make_float4(__uint_as_float(cvt_tf32(u0 - h0)),
                            __uint_as_float(cvt_tf32(u1 - h1)),
                            __uint_as_float(cvt_tf32(u2 - h2)),
                            __uint_as_float(cvt_tf32(u3 - h3)));
}

// Pass 1b: tf32-rounded V. One thread per float4: 1M threads.
__global__ void precompute_vh(const float* __restrict__ x){
    int idx = blockIdx.x*blockDim.x + threadIdx.x;
    int d4  = idx & 15;
    int bhs = idx >> 4;
    int s   = bhs & (SEQ-1);
    int bh  = bhs >> 10;
    int b = bh >> 3, h = bh & 7;
    float4 v = ((const float4*)x)[((size_t)(b*SEQ + s))*(EMB/4) + h*(DK/4) + d4];
    float4 o;
    o.x = __uint_as_float(cvt_tf32(v.x));
    o.y = __uint_as_float(cvt_tf32(v.y));
    o.z = __uint_as_float(cvt_tf32(v.z));
    o.w = __uint_as_float(cvt_tf32(v.w));
    ((float4*)g_vh)[idx] = o;
}

// Pass 2: QK via split-tf32 k4 MMAs -> product -> exp -> PV MMA -> normalize.
// 4 warps; warp w owns rows [w*32,w*32+32) as 2 m16 blocks. j-side u staged with
// column permutation phys(j)= j<4 ? 2j : 2j-7, making QK C-frag == PV A-frag
// (renaming c0,c2,c1,c3), no shuffles.
__global__ void __launch_bounds__(128, 2)
qk_attn7(float* __restrict__ out){
    __shared__ __align__(16) float sU[2][NP][TJ][4];   // [hi/lo][pair][phys j][comp]
    __shared__ __align__(16) float sVh[TJ*VSTR];

    const int bh = blockIdx.y, b = bh >> 3, h = bh & 7;
    const int tid = threadIdx.x;
    const int w   = tid >> 5;
    const int lane = tid & 31;
    const int g   = lane >> 2, tig = lane & 3;
    const int rowbase = blockIdx.x*TM + w*32;

    // i-side A-fragments: [blk][pair]: a0 = U(row rowbase+16blk+g, comp tig), a1 = +8
    unsigned aih[2][NP][2], ail[2][NP][2];
#pragma unroll
    for (int blk = 0; blk < 2; ++blk)
#pragma unroll
        for (int p = 0; p < NP; ++p){
            int r0 = rowbase + blk*16 + g;
            const float* uh0 = (const float*)&g_uh[(bh*NP + p)*SEQ + r0];
            const float* uh1 = (const float*)&g_uh[(bh*NP + p)*SEQ + r0 + 8];
            const float* ul0 = (const float*)&g_ul[(bh*NP + p)*SEQ + r0];
            const float* ul1 = (const float*)&g_ul[(bh*NP + p)*SEQ + r0 + 8];
            aih[blk][p][0] = __float_as_uint(uh0[tig]);
            aih[blk][p][1] = __float_as_uint(uh1[tig]);
            ail[blk][p][0] = __float_as_uint(ul0[tig]);
            ail[blk][p][1] = __float_as_uint(ul1[tig]);
        }

    float acc[2][8][4];
#pragma unroll
    for (int blk = 0; blk < 2; ++blk)
#pragma unroll
        for (int nb = 0; nb < 8; ++nb)
#pragma unroll
            for (int k = 0; k < 4; ++k) acc[blk][nb][k] = 0.f;
    float ps[4] = {0.f, 0.f, 0.f, 0.f};

    for (int jt = 0; jt < NT; ++jt){
        const int j0 = jt*TJ;
        // stage u tiles (512 float4, permuted cols): 4 per thread
#pragma unroll
        for (int r = 0; r < 4; ++r){
            int e  = tid + r*128;          // 0..511
            int hl = e >> 8;               // 0=hi, 1=lo
            int rem = e & 255;
            int p  = rem >> 6, jj = rem & 63;
            int j8 = jj & 7;
            int pj = (j8 < 4) ? (j8 << 1) : ((j8 << 1) - 7);
            int jphys = (jj & 56) | pj;
            float4 v = hl ? g_ul[(bh*NP + p)*SEQ + j0 + jj]
                          : g_uh[(bh*NP + p)*SEQ + j0 + jj];
            *(float4*)&sU[hl][p][jphys][0] = v;
        }
        // stage V tile (logical j): 1024 float4 -> 8 per thread
#pragma unroll
        for (int r = 0; r < 8; ++r){
            int l = tid + r*128;
            int row = l >> 4, c4 = l & 15;
            *(float4*)&sVh[row*VSTR + c4*4] =
                ((const float4*)g_vh)[((size_t)bh*SEQ + j0 + row)*(DK/4) + c4];
        }
        __syncthreads();

#pragma unroll
        for (int kb = 0; kb < 8; ++kb){
            // B-fragments: u_j (phys col g), comp tig — conflict-free
            unsigned bhf[NP], blf[NP];
#pragma unroll
            for (int p = 0; p < NP; ++p){
                bhf[p] = __float_as_uint(sU[0][p][kb*8 + g][tig]);
                blf[p] = __float_as_uint(sU[1][p][kb*8 + g][tig]);
            }
            // QK: 4 pair-dots per block, split-tf32 (hh + lh + hl)
            float qa[2][NP][4];
#pragma unroll
            for (int blk = 0; blk < 2; ++blk)
#pragma unroll
                for (int p = 0; p < NP; ++p){
                    MMA_K4_Z  (qa[blk][p], aih[blk][p][0], aih[blk][p][1], bhf[p]);
                    MMA_K4_ACC(qa[blk][p], ail[blk][p][0], ail[blk][p][1], bhf[p]);
                    MMA_K4_ACC(qa[blk][p], aih[blk][p][0], aih[blk][p][1], blf[p]);
                }
            // product over pairs, |.|, exp; C cols are permuted: c0->j=tig,
            // c1->j=tig+4 (row g); c2,c3 same for row g+8
            const float* vA = &sVh[(kb*8 + tig)*VSTR + g];
            const float* vB = &sVh[(kb*8 + tig + 4)*VSTR + g];
#pragma unroll
            for (int blk = 0; blk < 2; ++blk){
                float e0 = __expf(fabsf(qa[blk][0][0]*qa[blk][1][0]*qa[blk][2][0]*qa[blk][3][0]));
                float e1 = __expf(fabsf(qa[blk][0][1]*qa[blk][1][1]*qa[blk][2][1]*qa[blk][3][1]));
                float e2 = __expf(fabsf(qa[blk][0][2]*qa[blk][1][2]*qa[blk][2][2]*qa[blk][3][2]));
                float e3 = __expf(fabsf(qa[blk][0][3]*qa[blk][1][3]*qa[blk][2][3]*qa[blk][3][3]));
                ps[blk*2 + 0] += e0 + e1;   // row g:   j=tig, tig+4
                ps[blk*2 + 1] += e2 + e3;   // row g+8
                // PV A-frag = (c0, c2, c1, c3)
                unsigned pa0 = cvt_tf32(e0), pa1 = cvt_tf32(e2);
                unsigned pa2 = cvt_tf32(e1), pa3 = cvt_tf32(e3);
#pragma unroll
                for (int nb = 0; nb < 8; ++nb){
                    unsigned b0 = __float_as_uint(vA[nb*8]);
                    unsigned b1 = __float_as_uint(vB[nb*8]);
                    MMA_K8_ACC(acc[blk][nb], pa0, pa1, pa2, pa3, b0, b1);
                }
            }
        }
        __syncthreads();
    }

    // row sums: reduce over the 4 tig lanes
#pragma unroll
    for (int r = 0; r < 4; ++r){
        ps[r] += __shfl_xor_sync(0xffffffffu, ps[r], 1);
        ps[r] += __shfl_xor_sync(0xffffffffu, ps[r], 2);
    }
    const float inv0 = 1.0f/ps[0], inv1 = 1.0f/ps[1];
    const float inv2 = 1.0f/ps[2], inv3 = 1.0f/ps[3];

#pragma unroll
    for (int nb = 0; nb < 8; ++nb){
        size_t col = h*DK + nb*8 + 2*tig;
        size_t o0 = ((size_t)(b*SEQ + rowbase + g +  0))*EMB + col;
        size_t o1 = ((size_t)(b*SEQ + rowbase + g +  8))*EMB + col;
        size_t o2 = ((size_t)(b*SEQ + rowbase + g + 16))*EMB + col;
        size_t o3 = ((size_t)(b*SEQ + rowbase + g + 24))*EMB + col;
        *(float2*)&out[o0] = make_float2(acc[0][nb][0]*inv0, acc[0][nb][1]*inv0);
        *(float2*)&out[o1] = make_float2(acc[0][nb][2]*inv1, acc[0][nb][3]*inv1);
        *(float2*)&out[o2] = make_float2(acc[1][nb][0]*inv2, acc[1][nb][1]*inv2);
        *(float2*)&out[o3] = make_float2(acc[1][nb][2]*inv3, acc[1][nb][3]*inv3);
    }
}

extern "C" void kernel_launch(void* const* d_in, const int* in_sizes, int n_in,
                              void* d_out, int out_size){
    const float* x = (const float*)d_in[0];
    float* out = (float*)d_out;
    precompute_u<<<(BH*NP*SEQ)/256, 256>>>(x);
    precompute_vh<<<((size_t)BH*SEQ*16)/256, 256>>>(x);
    dim3 grid(SEQ/TM, BH);
    qk_attn7<<<grid, 128>>>(out);
}

// round 12
// speedup vs baseline: 1.6608x; 1.0812x over previous
#include <cuda_runtime.h>

#define BATCH 8
#define SEQ   1024
#define EMB   512
#define HEADS 8
#define DK    64
#define NW    8
#define NP    4            // wire pairs
#define BH    (BATCH*HEADS)
#define TM    128          // rows per CTA (4 warps x m=32)
#define TJ    64           // j-tile
#define NT    (SEQ/TJ)
#define VSTR  72           // V smem row stride: bank=(8*tig+g+8*nb)%32 conflict-free

// Precomputed tables (device globals; allocation is forbidden)
__device__ float4 g_uh[BH*NP*SEQ];          // pair u-vectors, tf32 hi
__device__ float4 g_ul[BH*NP*SEQ];          // tf32 lo residual
__device__ float  g_vh[(size_t)BH*SEQ*DK];  // V rounded to tf32

static __device__ __forceinline__ unsigned cvt_tf32(float f){
    unsigned r; asm("cvt.rna.tf32.f32 %0, %1;" : "=r"(r) : "f"(f)); return r;
}

// QK: m16n8k8, D = A*B (zero-init C). A=[ah|al], B=[bh|bh] -> ah.bh + al.bh
#define MMA_K8_Z(D, A0, A1, A2, A3, B0, B1)                                 \
    asm volatile("mma.sync.aligned.m16n8k8.row.col.f32.tf32.tf32.f32 "      \
        "{%0,%1,%2,%3}, {%4,%5,%6,%7}, {%8,%9}, {%10,%10,%10,%10};"         \
        : "=f"((D)[0]), "=f"((D)[1]), "=f"((D)[2]), "=f"((D)[3])            \
        : "r"(A0), "r"(A1), "r"(A2), "r"(A3), "r"(B0), "r"(B1), "f"(0.f))
// QK: m16n8k4, D += A*B  (the ah.bl correction)
#define MMA_K4_ACC(D, A0, A1, B)                                            \
    asm volatile("mma.sync.aligned.m16n8k4.row.col.f32.tf32.tf32.f32 "      \
        "{%0,%1,%2,%3}, {%4,%5}, {%6}, {%0,%1,%2,%3};"                      \
        : "+f"((D)[0]), "+f"((D)[1]), "+f"((D)[2]), "+f"((D)[3])            \
        : "r"(A0), "r"(A1), "r"(B))
// PV: m16n8k8, D += A*B
#define MMA_K8_ACC(D, A0, A1, A2, A3, B0, B1)                               \
    asm volatile("mma.sync.aligned.m16n8k8.row.col.f32.tf32.tf32.f32 "      \
        "{%0,%1,%2,%3}, {%4,%5,%6,%7}, {%8,%9}, {%0,%1,%2,%3};"             \
        : "+f"((D)[0]), "+f"((D)[1]), "+f"((D)[2]), "+f"((D)[3])            \
        : "r"(A0), "r"(A1), "r"(A2), "r"(A3), "r"(B0), "r"(B1))

// Pass 1a: pair u-vectors. One thread per (bh, pair, s): 256K threads.
// u = (ca*cb, ca*sb, sa*cb, sa*sb); dot(u_i,u_j) = cos((xa_i-xa_j)/2)*cos((xb_i-xb_j)/2)
__global__ void precompute_u(const float* __restrict__ x){
    int idx = blockIdx.x*blockDim.x + threadIdx.x;   // (bh*NP + p)*SEQ + s
    int s   = idx & (SEQ-1);
    int bhp = idx >> 10;
    int p   = bhp & (NP-1);
    int bh  = bhp >> 2;
    int b = bh >> 3, h = bh & 7;
    float2 xv = *(const float2*)&x[((size_t)(b*SEQ+s))*EMB + h*DK + 2*p];
    float sa, ca, sb, cb;
    sincosf(0.5f*xv.x, &sa, &ca);
    sincosf(0.5f*xv.y, &sb, &cb);
    float u0 = ca*cb, u1 = ca*sb, u2 = sa*cb, u3 = sa*sb;
    float h0 = __uint_as_float(cvt_tf32(u0));
    float h1 = __uint_as_float(cvt_tf32(u1));
    float h2 = __uint_as_float(cvt_tf32(u2));
    float h3 = __uint_as_float(cvt_tf32(u3));
    g_uh[idx] = make_float4(h0, h1, h2, h3);
    g_ul[idx] = make_float4(__uint_as_float(cvt_tf32(u0 - h0)),
                            __uint_as_float(cvt_tf32(u1 - h1)),
                            __uint_as_float(cvt_tf32(u2 - h2)),
                            __uint_as_float(cvt_tf32(u3 - h3)));
}

// Pass 1b: tf32-rounded V. One thread per float4: 1M threads.
__global__ void precompute_vh(const float* __restrict__ x){
    int idx = blockIdx.x*blockDim.x + threadIdx.x;
    int d4  = idx & 15;
    int bhs = idx >> 4;
    int s   = bhs & (SEQ-1);
    int bh  = bhs >> 10;
    int b = bh >> 3, h = bh & 7;
    float4 v = ((const float4*)x)[((size_t)(b*SEQ + s))*(EMB/4) + h*(DK/4) + d4];
    float4 o;
    o.x = __uint_as_float(cvt_tf32(v.x));
    o.y = __uint_as_float(cvt_tf32(v.y));
    o.z = __uint_as_float(cvt_tf32(v.z));
    o.w = __uint_as_float(cvt_tf32(v.w));
    ((float4*)g_vh)[idx] = o;
}

// Pass 2: QK via split-tf32 MMAs (k8 [ah|al]*[bh|bh] + k4 ah*bl) -> product ->
// exp -> PV MMA -> normalize. 4 warps; warp w owns rows [w*32,w*32+32) as 2 m16
// blocks. j-side u staged with column permutation phys(j)= j<4 ? 2j : 2j-7,
// making QK C-frag == PV A-frag (renaming c0,c2,c1,c3), no shuffles.
__global__ void __launch_bounds__(128, 2)
qk_attn8(float* __restrict__ out){
    __shared__ __align__(16) float sU[2][NP][TJ][4];   // [hi/lo][pair][phys j][comp]
    __shared__ __align__(16) float sVh[TJ*VSTR];

    const int bh = blockIdx.y, b = bh >> 3, h = bh & 7;
    const int tid = threadIdx.x;
    const int w   = tid >> 5;
    const int lane = tid & 31;
    const int g   = lane >> 2, tig = lane & 3;
    const int rowbase = blockIdx.x*TM + w*32;

    // i-side A-fragments: [blk][pair]
    unsigned aih[2][NP][2], ail[2][NP][2];
#pragma unroll
    for (int blk = 0; blk < 2; ++blk)
#pragma unroll
        for (int p = 0; p < NP; ++p){
            int r0 = rowbase + blk*16 + g;
            const float* uh0 = (const float*)&g_uh[(bh*NP + p)*SEQ + r0];
            const float* uh1 = (const float*)&g_uh[(bh*NP + p)*SEQ + r0 + 8];
            const float* ul0 = (const float*)&g_ul[(bh*NP + p)*SEQ + r0];
            const float* ul1 = (const float*)&g_ul[(bh*NP + p)*SEQ + r0 + 8];
            aih[blk][p][0] = __float_as_uint(uh0[tig]);
            aih[blk][p][1] = __float_as_uint(uh1[tig]);
            ail[blk][p][0] = __float_as_uint(ul0[tig]);
            ail[blk][p][1] = __float_as_uint(ul1[tig]);
        }

    float acc[2][8][4];
#pragma unroll
    for (int blk = 0; blk < 2; ++blk)
#pragma unroll
        for (int nb = 0; nb < 8; ++nb)
#pragma unroll
            for (int k = 0; k < 4; ++k) acc[blk][nb][k] = 0.f;
    float ps[4] = {0.f, 0.f, 0.f, 0.f};

    for (int jt = 0; jt < NT; ++jt){
        const int j0 = jt*TJ;
        // stage u tiles (512 float4, permuted cols): 4 per thread
#pragma unroll
        for (int r = 0; r < 4; ++r){
            int e  = tid + r*128;          // 0..511
            int hl = e >> 8;               // 0=hi, 1=lo
            int rem = e & 255;
            int p  = rem >> 6, jj = rem & 63;
            int j8 = jj & 7;
            int pj = (j8 < 4) ? (j8 << 1) : ((j8 << 1) - 7);
            int jphys = (jj & 56) | pj;
            float4 v = hl ? g_ul[(bh*NP + p)*SEQ + j0 + jj]
                          : g_uh[(bh*NP + p)*SEQ + j0 + jj];
            *(float4*)&sU[hl][p][jphys][0] = v;
        }
        // stage V tile (logical j): 1024 float4 -> 8 per thread
#pragma unroll
        for (int r = 0; r < 8; ++r){
            int l = tid + r*128;
            int row = l >> 4, c4 = l & 15;
            *(float4*)&sVh[row*VSTR + c4*4] =
                ((const float4*)g_vh)[((size_t)bh*SEQ + j0 + row)*(DK/4) + c4];
        }
        __syncthreads();

#pragma unroll
        for (int kb = 0; kb < 8; ++kb){
            // B-fragments: u_j (phys col g), comp tig — conflict-free
            unsigned bhf[NP], blf[NP];
#pragma unroll
            for (int p = 0; p < NP; ++p){
                bhf[p] = __float_as_uint(sU[0][p][kb*8 + g][tig]);
                blf[p] = __float_as_uint(sU[1][p][kb*8 + g][tig]);
            }
            // QK: 4 pair-dots per block, split packed into k:
            //   k8: [ah|al].[bh|bh] = ah.bh + al.bh  (B frag duplicated reg)
            //   k4: ah.bl
            float qa[2][NP][4];
#pragma unroll
            for (int blk = 0; blk < 2; ++blk)
#pragma unroll
                for (int p = 0; p < NP; ++p){
                    MMA_K8_Z  (qa[blk][p], aih[blk][p][0], aih[blk][p][1],
                                           ail[blk][p][0], ail[blk][p][1],
                                           bhf[p], bhf[p]);
                    MMA_K4_ACC(qa[blk][p], aih[blk][p][0], aih[blk][p][1], blf[p]);
                }
            // product over pairs, |.|, exp; C cols permuted: c0->j=tig,
            // c1->j=tig+4 (row g); c2,c3 same for row g+8
            const float* vA = &sVh[(kb*8 + tig)*VSTR + g];
            const float* vB = &sVh[(kb*8 + tig + 4)*VSTR + g];
#pragma unroll
            for (int blk = 0; blk < 2; ++blk){
                float e0 = __expf(fabsf(qa[blk][0][0]*qa[blk][1][0]*qa[blk][2][0]*qa[blk][3][0]));
                float e1 = __expf(fabsf(qa[blk][0][1]*qa[blk][1][1]*qa[blk][2][1]*qa[blk][3][1]));
                float e2 = __expf(fabsf(qa[blk][0][2]*qa[blk][1][2]*qa[blk][2][2]*qa[blk][3][2]));
                float e3 = __expf(fabsf(qa[blk][0][3]*qa[blk][1][3]*qa[blk][2][3]*qa[blk][3][3]));
                ps[blk*2 + 0] += e0 + e1;   // row g:   j=tig, tig+4
                ps[blk*2 + 1] += e2 + e3;   // row g+8
                // PV A-frag = (c0, c2, c1, c3)
                unsigned pa0 = cvt_tf32(e0), pa1 = cvt_tf32(e2);
                unsigned pa2 = cvt_tf32(e1), pa3 = cvt_tf32(e3);
#pragma unroll
                for (int nb = 0; nb < 8; ++nb){
                    unsigned b0 = __float_as_uint(vA[nb*8]);
                    unsigned b1 = __float_as_uint(vB[nb*8]);
                    MMA_K8_ACC(acc[blk][nb], pa0, pa1, pa2, pa3, b0, b1);
                }
            }
        }
        __syncthreads();
    }

    // row sums: reduce over the 4 tig lanes
#pragma unroll
    for (int r = 0; r < 4; ++r){
        ps[r] += __shfl_xor_sync(0xffffffffu, ps[r], 1);
        ps[r] += __shfl_xor_sync(0xffffffffu, ps[r], 2);
    }
    const float inv0 = 1.0f/ps[0], inv1 = 1.0f/ps[1];
    const float inv2 = 1.0f/ps[2], inv3 = 1.0f/ps[3];

#pragma unroll
    for (int nb = 0; nb < 8; ++nb){
        size_t col = h*DK + nb*8 + 2*tig;
        size_t o0 = ((size_t)(b*SEQ + rowbase + g +  0))*EMB + col;
        size_t o1 = ((size_t)(b*SEQ + rowbase + g +  8))*EMB + col;
        size_t o2 = ((size_t)(b*SEQ + rowbase + g + 16))*EMB + col;
        size_t o3 = ((size_t)(b*SEQ + rowbase + g + 24))*EMB + col;
        *(float2*)&out[o0] = make_float2(acc[0][nb][0]*inv0, acc[0][nb][1]*inv0);
        *(float2*)&out[o1] = make_float2(acc[0][nb][2]*inv1, acc[0][nb][3]*inv1);
        *(float2*)&out[o2] = make_float2(acc[1][nb][0]*inv2, acc[1][nb][1]*inv2);
        *(float2*)&out[o3] = make_float2(acc[1][nb][2]*inv3, acc[1][nb][3]*inv3);
    }
}

extern "C" void kernel_launch(void* const* d_in, const int* in_sizes, int n_in,
                              void* d_out, int out_size){
    const float* x = (const float*)d_in[0];
    float* out = (float*)d_out;
    precompute_u<<<(BH*NP*SEQ)/256, 256>>>(x);
    precompute_vh<<<((size_t)BH*SEQ*16)/256, 256>>>(x);
    dim3 grid(SEQ/TM, BH);
    qk_attn8<<<grid, 128>>>(out);
}

// round 13
// speedup vs baseline: 1.9930x; 1.2001x over previous
#include <cuda_runtime.h>
#include <cuda_fp16.h>

#define BATCH 8
#define SEQ   1024
#define EMB   512
#define HEADS 8
#define DK    64
#define NP    4            // wire pairs
#define BH    (BATCH*HEADS)
#define TM    128          // rows per CTA (4 warps x m=32)
#define TJ    64           // j-tile
#define NT    (SEQ/TJ)
#define VSTR2 72           // V smem row stride in u32: (8tig+g+8nb)%32 conflict-free

// Precomputed tables (device globals; allocation is forbidden)
// g_uq[(bh*NP+p)*SEQ+s] = {h01, h23, l01, l23} fp16x2-packed u-vector hi/lo
__device__ uint4    g_uq[BH*NP*SEQ];
// g_vp[(bh*512+jp)*64+col] = fp16x2 {V[2jp+1][col], V[2jp][col]}
__device__ unsigned g_vp[(size_t)BH*(SEQ/2)*DK];

static __device__ __forceinline__ unsigned pkf16(float hi, float lo){
    unsigned r; asm("cvt.rn.f16x2.f32 %0, %1, %2;" : "=r"(r) : "f"(hi), "f"(lo)); return r;
}

// m16n8k16 f16 MMA, f32 accum, zero C
#define MMA_F16_Z(D, A0, A1, A2, A3, B0, B1)                                \
    asm volatile("mma.sync.aligned.m16n8k16.row.col.f32.f16.f16.f32 "       \
        "{%0,%1,%2,%3}, {%4,%5,%6,%7}, {%8,%9}, {%10,%10,%10,%10};"         \
        : "=f"((D)[0]), "=f"((D)[1]), "=f"((D)[2]), "=f"((D)[3])            \
        : "r"(A0), "r"(A1), "r"(A2), "r"(A3), "r"(B0), "r"(B1), "f"(0.f))
// m16n8k16 f16 MMA, f32 accum, D += A*B
#define MMA_F16_ACC(D, A0, A1, A2, A3, B0, B1)                              \
    asm volatile("mma.sync.aligned.m16n8k16.row.col.f32.f16.f16.f32 "       \
        "{%0,%1,%2,%3}, {%4,%5,%6,%7}, {%8,%9}, {%0,%1,%2,%3};"             \
        : "+f"((D)[0]), "+f"((D)[1]), "+f"((D)[2]), "+f"((D)[3])            \
        : "r"(A0), "r"(A1), "r"(A2), "r"(A3), "r"(B0), "r"(B1))

// Pass 1a: u-vectors with fp16 hi/lo split. One thread per (bh, pair, s).
__global__ void precompute_u(const float* __restrict__ x){
    int idx = blockIdx.x*blockDim.x + threadIdx.x;   // (bh*NP + p)*SEQ + s
    int s   = idx & (SEQ-1);
    int bhp = idx >> 10;
    int p   = bhp & (NP-1);
    int bh  = bhp >> 2;
    int b = bh >> 3, h = bh & 7;
    float2 xv = *(const float2*)&x[((size_t)(b*SEQ+s))*EMB + h*DK + 2*p];
    float sa, ca, sb, cb;
    sincosf(0.5f*xv.x, &sa, &ca);
    sincosf(0.5f*xv.y, &sb, &cb);
    float u0 = ca*cb, u1 = ca*sb, u2 = sa*cb, u3 = sa*sb;
    float h0 = __half2float(__float2half_rn(u0));
    float h1 = __half2float(__float2half_rn(u1));
    float h2 = __half2float(__float2half_rn(u2));
    float h3 = __half2float(__float2half_rn(u3));
    g_uq[idx] = make_uint4(pkf16(u1 /*->rn f16*/, u0),
                           pkf16(u3, u2),
                           pkf16(u1 - h1, u0 - h0),
                           pkf16(u3 - h3, u2 - h2));
}

// Pass 1b: V as fp16x2 j-pair planes. One thread per (bh, jp, col): 2M threads.
__global__ void precompute_v(const float* __restrict__ x){
    int idx = blockIdx.x*blockDim.x + threadIdx.x;   // (bh*512 + jp)*64 + col
    int col = idx & 63;
    int jp  = (idx >> 6) & 511;
    int bh  = idx >> 15;
    int b = bh >> 3, h = bh & 7;
    float v0 = x[((size_t)(b*SEQ + 2*jp    ))*EMB + h*DK + col];
    float v1 = x[((size_t)(b*SEQ + 2*jp + 1))*EMB + h*DK + col];
    g_vp[idx] = pkf16(v1, v0);
}

// Pass 2: QK (fp16-split k16 MMA) -> product -> exp -> PV (fp16 k16 over 16 j)
// -> normalize. 4 warps; warp w owns rows [w*32,w*32+32) as 2 m16 blocks.
__global__ void __launch_bounds__(128, 3)
qk_attn9(float* __restrict__ out){
    __shared__ __align__(16) uint4    sU[NP][TJ];       // compact u [h4|l4]
    __shared__ __align__(16) unsigned sV[32*VSTR2];     // fp16x2 j-pairs

    const int bh = blockIdx.y, b = bh >> 3, h = bh & 7;
    const int tid = threadIdx.x;
    const int w   = tid >> 5;
    const int lane = tid & 31;
    const int g   = lane >> 2, tig = lane & 3;
    const int rowbase = blockIdx.x*TM + w*32;
    const bool lo2 = (tig < 2);

    // i-side A-frag bases: a0 = compact[tig] of row, a1 = row+8 (a2/a3 derived)
    unsigned ai0[2][NP], ai1[2][NP];
    {
        const unsigned* gu = (const unsigned*)g_uq;
#pragma unroll
        for (int blk = 0; blk < 2; ++blk)
#pragma unroll
            for (int p = 0; p < NP; ++p){
                int row = rowbase + blk*16 + g;
                size_t base = ((size_t)(bh*NP + p)*SEQ + row)*4 + tig;
                ai0[blk][p] = gu[base];
                ai1[blk][p] = gu[base + 32];   // row+8 -> +8*4 u32
            }
    }

    float acc[2][8][4];
#pragma unroll
    for (int blk = 0; blk < 2; ++blk)
#pragma unroll
        for (int nb = 0; nb < 8; ++nb)
#pragma unroll
            for (int k = 0; k < 4; ++k) acc[blk][nb][k] = 0.f;
    float ps[4] = {0.f, 0.f, 0.f, 0.f};

    for (int jt = 0; jt < NT; ++jt){
        const int j0 = jt*TJ;
        // stage u tiles: NP*TJ = 256 uint4 -> 2 per thread
#pragma unroll
        for (int r = 0; r < 2; ++r){
            int e = tid + r*128;
            int p = e >> 6, jj = e & 63;
            sU[p][jj] = g_uq[(size_t)(bh*NP + p)*SEQ + j0 + jj];
        }
        // stage V tile: 32 jp x 64 col u32 = 512 uint4 -> 4 per thread
#pragma unroll
        for (int r = 0; r < 4; ++r){
            int l = tid + r*128;
            int row = l >> 4, c4 = l & 15;
            *(uint4*)&sV[row*VSTR2 + c4*4] =
                ((const uint4*)g_vp)[((size_t)bh*512 + (j0 >> 1) + row)*16 + c4];
        }
        __syncthreads();

#pragma unroll
        for (int m = 0; m < 4; ++m){            // kb-pairs: j = 16m .. 16m+15
            unsigned pa[2][4];                  // PV A-frags per blk
#pragma unroll
            for (int half = 0; half < 2; ++half){
                const int kb = 2*m + half;
                float q0[4], q1[4];
#pragma unroll
                for (int p = 0; p < NP; ++p){
                    uint4 su = sU[p][kb*8 + g];
                    unsigned b0 = (tig & 1) ? su.y : su.x;
                    unsigned b1 = lo2 ? ((tig & 1) ? su.w : su.z) : 0u;
                    {
                        unsigned a0 = ai0[0][p], a1 = ai1[0][p];
                        unsigned a2 = lo2 ? a0 : 0u, a3 = lo2 ? a1 : 0u;
                        float d[4];
                        MMA_F16_Z(d, a0, a1, a2, a3, b0, b1);
                        if (p == 0){ q0[0]=d[0]; q0[1]=d[1]; q0[2]=d[2]; q0[3]=d[3]; }
                        else       { q0[0]*=d[0]; q0[1]*=d[1]; q0[2]*=d[2]; q0[3]*=d[3]; }
                    }
                    {
                        unsigned a0 = ai0[1][p], a1 = ai1[1][p];
                        unsigned a2 = lo2 ? a0 : 0u, a3 = lo2 ? a1 : 0u;
                        float d[4];
                        MMA_F16_Z(d, a0, a1, a2, a3, b0, b1);
                        if (p == 0){ q1[0]=d[0]; q1[1]=d[1]; q1[2]=d[2]; q1[3]=d[3]; }
                        else       { q1[0]*=d[0]; q1[1]*=d[1]; q1[2]*=d[2]; q1[3]*=d[3]; }
                    }
                }
                // diagonal score = 1 is the softmax max -> raw exp is safe
                {
                    float e0 = __expf(fabsf(q0[0]));   // row g,   col 2tig
                    float e1 = __expf(fabsf(q0[1]));   // row g,   col 2tig+1
                    float e2 = __expf(fabsf(q0[2]));   // row g+8, col 2tig
                    float e3 = __expf(fabsf(q0[3]));
                    ps[0] += e0 + e1; ps[1] += e2 + e3;
                    pa[0][half*2 + 0] = pkf16(e1, e0);
                    pa[0][half*2 + 1] = pkf16(e3, e2);
                }
                {
                    float e0 = __expf(fabsf(q1[0]));
                    float e1 = __expf(fabsf(q1[1]));
                    float e2 = __expf(fabsf(q1[2]));
                    float e3 = __expf(fabsf(q1[3]));
                    ps[2] += e0 + e1; ps[3] += e2 + e3;
                    pa[1][half*2 + 0] = pkf16(e1, e0);
                    pa[1][half*2 + 1] = pkf16(e3, e2);
                }
            }
            // PV over 16 j: B-frags from fp16x2 j-pair plane, shared across blks
#pragma unroll
            for (int nb = 0; nb < 8; ++nb){
                unsigned b0 = sV[(m*8 + tig)*VSTR2     + g + 8*nb];
                unsigned b1 = sV[(m*8 + 4 + tig)*VSTR2 + g + 8*nb];
                MMA_F16_ACC(acc[0][nb], pa[0][0], pa[0][1], pa[0][2], pa[0][3], b0, b1);
                MMA_F16_ACC(acc[1][nb], pa[1][0], pa[1][1], pa[1][2], pa[1][3], b0, b1);
            }
        }
        __syncthreads();
    }

    // row sums: reduce over the 4 tig lanes
#pragma unroll
    for (int r = 0; r < 4; ++r){
        ps[r] += __shfl_xor_sync(0xffffffffu, ps[r], 1);
        ps[r] += __shfl_xor_sync(0xffffffffu, ps[r], 2);
    }
    const float inv0 = 1.0f/ps[0], inv1 = 1.0f/ps[1];
    const float inv2 = 1.0f/ps[2], inv3 = 1.0f/ps[3];

#pragma unroll
    for (int nb = 0; nb < 8; ++nb){
        size_t col = h*DK + nb*8 + 2*tig;
        size_t o0 = ((size_t)(b*SEQ + rowbase + g +  0))*EMB + col;
        size_t o1 = ((size_t)(b*SEQ + rowbase + g +  8))*EMB + col;
        size_t o2 = ((size_t)(b*SEQ + rowbase + g + 16))*EMB + col;
        size_t o3 = ((size_t)(b*SEQ + rowbase + g + 24))*EMB + col;
        *(float2*)&out[o0] = make_float2(acc[0][nb][0]*inv0, acc[0][nb][1]*inv0);
        *(float2*)&out[o1] = make_float2(acc[0][nb][2]*inv1, acc[0][nb][3]*inv1);
        *(float2*)&out[o2] = make_float2(acc[1][nb][0]*inv2, acc[1][nb][1]*inv2);
        *(float2*)&out[o3] = make_float2(acc[1][nb][2]*inv3, acc[1][nb][3]*inv3);
    }
}

extern "C" void kernel_launch(void* const* d_in, const int* in_sizes, int n_in,
                              void* d_out, int out_size){
    const float* x = (const float*)d_in[0];
    float* out = (float*)d_out;
    precompute_u<<<(BH*NP*SEQ)/256, 256>>>(x);
    precompute_v<<<(BH*(SEQ/2)*DK)/256, 256>>>(x);
    dim3 grid(SEQ/TM, BH);
    qk_attn9<<<grid, 128>>>(out);
}

// round 14
// speedup vs baseline: 2.4994x; 1.2541x over previous
#include <cuda_runtime.h>
#include <cuda_fp16.h>

#define BATCH 8
#define SEQ   1024
#define EMB   512
#define HEADS 8
#define DK    64
#define NP    4            // wire pairs
#define BH    (BATCH*HEADS)
#define TM    128          // rows per CTA (4 warps x m=32)
#define TJ    64           // j-tile
#define NT    (SEQ/TJ)
#define VSTR2 72           // V smem row stride in u32: (8tig+g+8nb)%32 conflict-free

// sqrt(log2(e)): both i- and j-side u for pair 0 carry this factor, so the
// pair-0 dot (hence the whole score product) is scaled by log2(e) exactly once.
#define SQRT_LOG2E 1.2011224087864498f

// Precomputed tables (device globals; allocation is forbidden)
// g_uq[(bh*NP+p)*SEQ+s] = {h01, h23, l01, l23}  (i-side A-fragment layout)
__device__ uint4 g_uq[BH*NP*SEQ];
// g_ub[((bh*NP+p)*SEQ+s)*2+c] = {h, l} for comp-half c (j-side B-fragment layout)
__device__ uint2 g_ub[BH*NP*SEQ*2];
// g_vp[(bh*512+jp)*64+col] = fp16x2 {V[2jp+1][col], V[2jp][col]}
__device__ unsigned g_vp[(size_t)BH*(SEQ/2)*DK];

static __device__ __forceinline__ unsigned pkf16(float hi, float lo){
    unsigned r; asm("cvt.rn.f16x2.f32 %0, %1, %2;" : "=r"(r) : "f"(hi), "f"(lo)); return r;
}
static __device__ __forceinline__ float ex2f(float x){
    float r; asm("ex2.approx.f32 %0, %1;" : "=f"(r) : "f"(x)); return r;
}

// m16n8k16 f16 MMA, f32 accum, zero C
#define MMA_F16_Z(D, A0, A1, A2, A3, B0, B1)                                \
    asm volatile("mma.sync.aligned.m16n8k16.row.col.f32.f16.f16.f32 "       \
        "{%0,%1,%2,%3}, {%4,%5,%6,%7}, {%8,%9}, {%10,%10,%10,%10};"         \
        : "=f"((D)[0]), "=f"((D)[1]), "=f"((D)[2]), "=f"((D)[3])            \
        : "r"(A0), "r"(A1), "r"(A2), "r"(A3), "r"(B0), "r"(B1), "f"(0.f))
// m16n8k16 f16 MMA, f32 accum, D += A*B
#define MMA_F16_ACC(D, A0, A1, A2, A3, B0, B1)                              \
    asm volatile("mma.sync.aligned.m16n8k16.row.col.f32.f16.f16.f32 "       \
        "{%0,%1,%2,%3}, {%4,%5,%6,%7}, {%8,%9}, {%0,%1,%2,%3};"             \
        : "+f"((D)[0]), "+f"((D)[1]), "+f"((D)[2]), "+f"((D)[3])            \
        : "r"(A0), "r"(A1), "r"(A2), "r"(A3), "r"(B0), "r"(B1))

// Pass 1a: u-vectors with fp16 hi/lo split (pair 0 pre-scaled by sqrt(log2e)).
__global__ void precompute_u(const float* __restrict__ x){
    int idx = blockIdx.x*blockDim.x + threadIdx.x;   // (bh*NP + p)*SEQ + s
    int s   = idx & (SEQ-1);
    int bhp = idx >> 10;
    int p   = bhp & (NP-1);
    int bh  = bhp >> 2;
    int b = bh >> 3, h = bh & 7;
    float2 xv = *(const float2*)&x[((size_t)(b*SEQ+s))*EMB + h*DK + 2*p];
    float sa, ca, sb, cb;
    sincosf(0.5f*xv.x, &sa, &ca);
    sincosf(0.5f*xv.y, &sb, &cb);
    float sc = (p == 0) ? SQRT_LOG2E : 1.0f;
    float u0 = sc*ca*cb, u1 = sc*ca*sb, u2 = sc*sa*cb, u3 = sc*sa*sb;
    float h0 = __half2float(__float2half_rn(u0));
    float h1 = __half2float(__float2half_rn(u1));
    float h2 = __half2float(__float2half_rn(u2));
    float h3 = __half2float(__float2half_rn(u3));
    unsigned h01 = pkf16(u1, u0), h23 = pkf16(u3, u2);
    unsigned l01 = pkf16(u1 - h1, u0 - h0), l23 = pkf16(u3 - h3, u2 - h2);
    g_uq[idx] = make_uint4(h01, h23, l01, l23);
    g_ub[idx*2 + 0] = make_uint2(h01, l01);
    g_ub[idx*2 + 1] = make_uint2(h23, l23);
}

// Pass 1b: V as fp16x2 j-pair planes. One thread per (bh, jp, col): 2M threads.
__global__ void precompute_v(const float* __restrict__ x){
    int idx = blockIdx.x*blockDim.x + threadIdx.x;   // (bh*512 + jp)*64 + col
    int col = idx & 63;
    int jp  = (idx >> 6) & 511;
    int bh  = idx >> 15;
    int b = bh >> 3, h = bh & 7;
    float v0 = x[((size_t)(b*SEQ + 2*jp    ))*EMB + h*DK + col];
    float v1 = x[((size_t)(b*SEQ + 2*jp + 1))*EMB + h*DK + col];
    g_vp[idx] = pkf16(v1, v0);
}

// Pass 2: QK (fp16-split k16 MMA) -> product -> ex2 -> PV (fp16 k16 over 16 j)
// -> normalize. 4 warps; warp w owns rows [w*32,w*32+32) as 2 m16 blocks.
__global__ void __launch_bounds__(128, 4)
qk_attn10(float* __restrict__ out){
    __shared__ __align__(16) uint2    sUB[NP][TJ][2];   // j-side {h,l} per comp-half
    __shared__ __align__(16) unsigned sV[32*VSTR2];     // fp16x2 j-pairs

    const int bh = blockIdx.y, b = bh >> 3, h = bh & 7;
    const int tid = threadIdx.x;
    const int w   = tid >> 5;
    const int lane = tid & 31;
    const int g   = lane >> 2, tig = lane & 3;
    const int rowbase = blockIdx.x*TM + w*32;
    const bool lo2 = (tig < 2);
    const int chalf = tig & 1;

    // i-side A-frag bases: a0 = compact[tig] of row, a1 = row+8
    unsigned ai0[2][NP], ai1[2][NP];
    {
        const unsigned* gu = (const unsigned*)g_uq;
#pragma unroll
        for (int blk = 0; blk < 2; ++blk)
#pragma unroll
            for (int p = 0; p < NP; ++p){
                int row = rowbase + blk*16 + g;
                size_t base = ((size_t)(bh*NP + p)*SEQ + row)*4 + tig;
                ai0[blk][p] = gu[base];
                ai1[blk][p] = gu[base + 32];   // row+8 -> +8*4 u32
            }
    }

    float acc[2][8][4];
#pragma unroll
    for (int blk = 0; blk < 2; ++blk)
#pragma unroll
        for (int nb = 0; nb < 8; ++nb)
#pragma unroll
            for (int k = 0; k < 4; ++k) acc[blk][nb][k] = 0.f;
    float ps[4] = {0.f, 0.f, 0.f, 0.f};

    for (int jt = 0; jt < NT; ++jt){
        const int j0 = jt*TJ;
        // stage j-side u: NP*TJ entries of 16 B -> 2 uint4 per thread
#pragma unroll
        for (int r = 0; r < 2; ++r){
            int e = tid + r*128;
            int p = e >> 6, jj = e & 63;
            *(uint4*)&sUB[p][jj][0] =
                ((const uint4*)g_ub)[(size_t)(bh*NP + p)*SEQ + j0 + jj];
        }
        // stage V tile: 32 jp x 64 col u32 = 512 uint4 -> 4 per thread
#pragma unroll
        for (int r = 0; r < 4; ++r){
            int l = tid + r*128;
            int row = l >> 4, c4 = l & 15;
            *(uint4*)&sV[row*VSTR2 + c4*4] =
                ((const uint4*)g_vp)[((size_t)bh*512 + (j0 >> 1) + row)*16 + c4];
        }
        __syncthreads();

#pragma unroll
        for (int m = 0; m < 4; ++m){            // kb-pairs: j = 16m .. 16m+15
            unsigned pa[2][4];                  // PV A-frags per blk
#pragma unroll
            for (int half = 0; half < 2; ++half){
                const int kb = 2*m + half;
                float q0[4], q1[4];
#pragma unroll
                for (int p = 0; p < NP; ++p){
                    uint2 ub = sUB[p][kb*8 + g][chalf];   // LDS.64, exact bytes
                    unsigned b0 = ub.x;
                    unsigned b1 = lo2 ? ub.y : 0u;
                    {
                        unsigned a0 = ai0[0][p], a1 = ai1[0][p];
                        unsigned a2 = lo2 ? a0 : 0u, a3 = lo2 ? a1 : 0u;
                        float d[4];
                        MMA_F16_Z(d, a0, a1, a2, a3, b0, b1);
                        if (p == 0){ q0[0]=d[0]; q0[1]=d[1]; q0[2]=d[2]; q0[3]=d[3]; }
                        else       { q0[0]*=d[0]; q0[1]*=d[1]; q0[2]*=d[2]; q0[3]*=d[3]; }
                    }
                    {
                        unsigned a0 = ai0[1][p], a1 = ai1[1][p];
                        unsigned a2 = lo2 ? a0 : 0u, a3 = lo2 ? a1 : 0u;
                        float d[4];
                        MMA_F16_Z(d, a0, a1, a2, a3, b0, b1);
                        if (p == 0){ q1[0]=d[0]; q1[1]=d[1]; q1[2]=d[2]; q1[3]=d[3]; }
                        else       { q1[0]*=d[0]; q1[1]*=d[1]; q1[2]*=d[2]; q1[3]*=d[3]; }
                    }
                }
                // q already carries log2e; diagonal max=1 -> raw ex2 is safe
                {
                    float e0 = ex2f(fabsf(q0[0]));   // row g,   col 2tig
                    float e1 = ex2f(fabsf(q0[1]));   // row g,   col 2tig+1
                    float e2 = ex2f(fabsf(q0[2]));   // row g+8, col 2tig
                    float e3 = ex2f(fabsf(q0[3]));
                    ps[0] += e0 + e1; ps[1] += e2 + e3;
                    pa[0][half*2 + 0] = pkf16(e1, e0);
                    pa[0][half*2 + 1] = pkf16(e3, e2);
                }
                {
                    float e0 = ex2f(fabsf(q1[0]));
                    float e1 = ex2f(fabsf(q1[1]));
                    float e2 = ex2f(fabsf(q1[2]));
                    float e3 = ex2f(fabsf(q1[3]));
                    ps[2] += e0 + e1; ps[3] += e2 + e3;
                    pa[1][half*2 + 0] = pkf16(e1, e0);
                    pa[1][half*2 + 1] = pkf16(e3, e2);
                }
            }
            // PV over 16 j: B-frags from fp16x2 j-pair plane, shared across blks
#pragma unroll
            for (int nb = 0; nb < 8; ++nb){
                unsigned b0 = sV[(m*8 + tig)*VSTR2     + g + 8*nb];
                unsigned b1 = sV[(m*8 + 4 + tig)*VSTR2 + g + 8*nb];
                MMA_F16_ACC(acc[0][nb], pa[0][0], pa[0][1], pa[0][2], pa[0][3], b0, b1);
                MMA_F16_ACC(acc[1][nb], pa[1][0], pa[1][1], pa[1][2], pa[1][3], b0, b1);
            }
        }
        __syncthreads();
    }

    // row sums: reduce over the 4 tig lanes
#pragma unroll
    for (int r = 0; r < 4; ++r){
        ps[r] += __shfl_xor_sync(0xffffffffu, ps[r], 1);
        ps[r] += __shfl_xor_sync(0xffffffffu, ps[r], 2);
    }
    const float inv0 = 1.0f/ps[0], inv1 = 1.0f/ps[1];
    const float inv2 = 1.0f/ps[2], inv3 = 1.0f/ps[3];

#pragma unroll
    for (int nb = 0; nb < 8; ++nb){
        size_t col = h*DK + nb*8 + 2*tig;
        size_t o0 = ((size_t)(b*SEQ + rowbase + g +  0))*EMB + col;
        size_t o1 = ((size_t)(b*SEQ + rowbase + g +  8))*EMB + col;
        size_t o2 = ((size_t)(b*SEQ + rowbase + g + 16))*EMB + col;
        size_t o3 = ((size_t)(b*SEQ + rowbase + g + 24))*EMB + col;
        *(float2*)&out[o0] = make_float2(acc[0][nb][0]*inv0, acc[0][nb][1]*inv0);
        *(float2*)&out[o1] = make_float2(acc[0][nb][2]*inv1, acc[0][nb][3]*inv1);
        *(float2*)&out[o2] = make_float2(acc[1][nb][0]*inv2, acc[1][nb][1]*inv2);
        *(float2*)&out[o3] = make_float2(acc[1][nb][2]*inv3, acc[1][nb][3]*inv3);
    }
}

extern "C" void kernel_launch(void* const* d_in, const int* in_sizes, int n_in,
                              void* d_out, int out_size){
    const float* x = (const float*)d_in[0];
    float* out = (float*)d_out;
    precompute_u<<<(BH*NP*SEQ)/256, 256>>>(x);
    precompute_v<<<(BH*(SEQ/2)*DK)/256, 256>>>(x);
    dim3 grid(SEQ/TM, BH);
    qk_attn10<<<grid, 128>>>(out);
}

// round 15
// speedup vs baseline: 2.6017x; 1.0409x over previous
#include <cuda_runtime.h>
#include <cuda_fp16.h>

#define BATCH 8
#define SEQ   1024
#define EMB   512
#define HEADS 8
#define DK    64
#define NP    4            // wire pairs
#define BH    (BATCH*HEADS)
#define TM    128          // rows per CTA (4 warps x m=32)
#define TJ    64           // j-tile
#define NT    (SEQ/TJ)
#define VSTR2 72           // V smem row stride in u32: (8tig+g+8nb)%32 conflict-free

// sqrt(log2(e)): pair-0 u carries this on both sides -> score scaled by log2(e).
#define SQRT_LOG2E 1.2011224087864498f
#define ONES_H2   0x3C003C00u   // fp16x2 {1.0, 1.0}

// Precomputed tables (device globals; allocation is forbidden)
__device__ uint4 g_uq[BH*NP*SEQ];        // i-side {h01,h23,l01,l23}
__device__ uint2 g_ub[BH*NP*SEQ*2];      // j-side {h,l} per comp-half
__device__ unsigned g_vp[(size_t)BH*(SEQ/2)*DK];  // fp16x2 {V[2jp+1], V[2jp]}

static __device__ __forceinline__ unsigned pkf16(float hi, float lo){
    unsigned r; asm("cvt.rn.f16x2.f32 %0, %1, %2;" : "=r"(r) : "f"(hi), "f"(lo)); return r;
}
static __device__ __forceinline__ unsigned ex2h2(unsigned x){
    unsigned r; asm("ex2.approx.f16x2 %0, %1;" : "=r"(r) : "r"(x)); return r;
}

// m16n8k16 f16 MMA, f32 accum, zero C
#define MMA_F16_Z(D, A0, A1, A2, A3, B0, B1)                                \
    asm volatile("mma.sync.aligned.m16n8k16.row.col.f32.f16.f16.f32 "       \
        "{%0,%1,%2,%3}, {%4,%5,%6,%7}, {%8,%9}, {%10,%10,%10,%10};"         \
        : "=f"((D)[0]), "=f"((D)[1]), "=f"((D)[2]), "=f"((D)[3])            \
        : "r"(A0), "r"(A1), "r"(A2), "r"(A3), "r"(B0), "r"(B1), "f"(0.f))
// m16n8k16 f16 MMA, f32 accum, D += A*B
#define MMA_F16_ACC(D, A0, A1, A2, A3, B0, B1)                              \
    asm volatile("mma.sync.aligned.m16n8k16.row.col.f32.f16.f16.f32 "       \
        "{%0,%1,%2,%3}, {%4,%5,%6,%7}, {%8,%9}, {%0,%1,%2,%3};"             \
        : "+f"((D)[0]), "+f"((D)[1]), "+f"((D)[2]), "+f"((D)[3])            \
        : "r"(A0), "r"(A1), "r"(A2), "r"(A3), "r"(B0), "r"(B1))

// Pass 1 (fused): blocks [0,1024) build u tables; blocks [1024,9216) build V.
__global__ void precompute_all(const float* __restrict__ x){
    if (blockIdx.x < 1024){
        int idx = blockIdx.x*blockDim.x + threadIdx.x;   // (bh*NP + p)*SEQ + s
        int s   = idx & (SEQ-1);
        int bhp = idx >> 10;
        int p   = bhp & (NP-1);
        int bh  = bhp >> 2;
        int b = bh >> 3, h = bh & 7;
        float2 xv = *(const float2*)&x[((size_t)(b*SEQ+s))*EMB + h*DK + 2*p];
        float sa, ca, sb, cb;
        sincosf(0.5f*xv.x, &sa, &ca);
        sincosf(0.5f*xv.y, &sb, &cb);
        float sc = (p == 0) ? SQRT_LOG2E : 1.0f;
        float u0 = sc*ca*cb, u1 = sc*ca*sb, u2 = sc*sa*cb, u3 = sc*sa*sb;
        float h0 = __half2float(__float2half_rn(u0));
        float h1 = __half2float(__float2half_rn(u1));
        float h2 = __half2float(__float2half_rn(u2));
        float h3 = __half2float(__float2half_rn(u3));
        unsigned h01 = pkf16(u1, u0), h23 = pkf16(u3, u2);
        unsigned l01 = pkf16(u1 - h1, u0 - h0), l23 = pkf16(u3 - h3, u2 - h2);
        g_uq[idx] = make_uint4(h01, h23, l01, l23);
        g_ub[idx*2 + 0] = make_uint2(h01, l01);
        g_ub[idx*2 + 1] = make_uint2(h23, l23);
    } else {
        int idx = (blockIdx.x - 1024)*blockDim.x + threadIdx.x; // (bh*512+jp)*64+col
        int col = idx & 63;
        int jp  = (idx >> 6) & 511;
        int bh  = idx >> 15;
        int b = bh >> 3, h = bh & 7;
        float v0 = x[((size_t)(b*SEQ + 2*jp    ))*EMB + h*DK + col];
        float v1 = x[((size_t)(b*SEQ + 2*jp + 1))*EMB + h*DK + col];
        g_vp[idx] = pkf16(v1, v0);
    }
}

// Pass 2: QK (fp16-split k16 MMA) -> f16x2 ex2 -> PV + ones-column sum MMA
// -> normalize. 4 warps; warp w owns rows [w*32,w*32+32) as 2 m16 blocks.
__global__ void __launch_bounds__(128, 4)
qk_attn11(float* __restrict__ out){
    __shared__ __align__(16) uint2    sUB[NP][TJ][2];   // j-side {h,l} per comp-half
    __shared__ __align__(16) unsigned sV[32*VSTR2];     // fp16x2 j-pairs

    const int bh = blockIdx.y, b = bh >> 3, h = bh & 7;
    const int tid = threadIdx.x;
    const int w   = tid >> 5;
    const int lane = tid & 31;
    const int g   = lane >> 2, tig = lane & 3;
    const int rowbase = blockIdx.x*TM + w*32;
    const bool lo2 = (tig < 2);
    const int chalf = tig & 1;

    // i-side A-frag bases
    unsigned ai0[2][NP], ai1[2][NP];
    {
        const unsigned* gu = (const unsigned*)g_uq;
#pragma unroll
        for (int blk = 0; blk < 2; ++blk)
#pragma unroll
            for (int p = 0; p < NP; ++p){
                int row = rowbase + blk*16 + g;
                size_t base = ((size_t)(bh*NP + p)*SEQ + row)*4 + tig;
                ai0[blk][p] = gu[base];
                ai1[blk][p] = gu[base + 32];
            }
    }

    float acc[2][8][4];
    float acc2[2][4];   // ones-column row sums: [blk]{row g: c0, row g+8: c2}
#pragma unroll
    for (int blk = 0; blk < 2; ++blk){
#pragma unroll
        for (int nb = 0; nb < 8; ++nb)
#pragma unroll
            for (int k = 0; k < 4; ++k) acc[blk][nb][k] = 0.f;
#pragma unroll
        for (int k = 0; k < 4; ++k) acc2[blk][k] = 0.f;
    }

    for (int jt = 0; jt < NT; ++jt){
        const int j0 = jt*TJ;
#pragma unroll
        for (int r = 0; r < 2; ++r){
            int e = tid + r*128;
            int p = e >> 6, jj = e & 63;
            *(uint4*)&sUB[p][jj][0] =
                ((const uint4*)g_ub)[(size_t)(bh*NP + p)*SEQ + j0 + jj];
        }
#pragma unroll
        for (int r = 0; r < 4; ++r){
            int l = tid + r*128;
            int row = l >> 4, c4 = l & 15;
            *(uint4*)&sV[row*VSTR2 + c4*4] =
                ((const uint4*)g_vp)[((size_t)bh*512 + (j0 >> 1) + row)*16 + c4];
        }
        __syncthreads();

#pragma unroll
        for (int m = 0; m < 4; ++m){            // kb-pairs: j = 16m .. 16m+15
            unsigned pa[2][4];                  // PV A-frags per blk
#pragma unroll
            for (int half = 0; half < 2; ++half){
                const int kb = 2*m + half;
                float q0[4], q1[4];
#pragma unroll
                for (int p = 0; p < NP; ++p){
                    uint2 ub = sUB[p][kb*8 + g][chalf];
                    unsigned b0 = ub.x;
                    unsigned b1 = lo2 ? ub.y : 0u;
                    {
                        unsigned a0 = ai0[0][p], a1 = ai1[0][p];
                        unsigned a2 = lo2 ? a0 : 0u, a3 = lo2 ? a1 : 0u;
                        float d[4];
                        MMA_F16_Z(d, a0, a1, a2, a3, b0, b1);
                        if (p == 0){ q0[0]=d[0]; q0[1]=d[1]; q0[2]=d[2]; q0[3]=d[3]; }
                        else       { q0[0]*=d[0]; q0[1]*=d[1]; q0[2]*=d[2]; q0[3]*=d[3]; }
                    }
                    {
                        unsigned a0 = ai0[1][p], a1 = ai1[1][p];
                        unsigned a2 = lo2 ? a0 : 0u, a3 = lo2 ? a1 : 0u;
                        float d[4];
                        MMA_F16_Z(d, a0, a1, a2, a3, b0, b1);
                        if (p == 0){ q1[0]=d[0]; q1[1]=d[1]; q1[2]=d[2]; q1[3]=d[3]; }
                        else       { q1[0]*=d[0]; q1[1]*=d[1]; q1[2]*=d[2]; q1[3]*=d[3]; }
                    }
                }
                // q carries log2e; |.| via sign-mask; 2 exps per MUFU op.
                // pa layout: {row g: cols 2tig,2tig+1} then {row g+8: same}.
                pa[0][half*2 + 0] = ex2h2(pkf16(q0[1], q0[0]) & 0x7FFF7FFFu);
                pa[0][half*2 + 1] = ex2h2(pkf16(q0[3], q0[2]) & 0x7FFF7FFFu);
                pa[1][half*2 + 0] = ex2h2(pkf16(q1[1], q1[0]) & 0x7FFF7FFFu);
                pa[1][half*2 + 1] = ex2h2(pkf16(q1[3], q1[2]) & 0x7FFF7FFFu);
            }
            // PV over 16 j + ones-column row-sum MMA (B = 1.0 constant)
#pragma unroll
            for (int nb = 0; nb < 8; ++nb){
                unsigned b0 = sV[(m*8 + tig)*VSTR2     + g + 8*nb];
                unsigned b1 = sV[(m*8 + 4 + tig)*VSTR2 + g + 8*nb];
                MMA_F16_ACC(acc[0][nb], pa[0][0], pa[0][1], pa[0][2], pa[0][3], b0, b1);
                MMA_F16_ACC(acc[1][nb], pa[1][0], pa[1][1], pa[1][2], pa[1][3], b0, b1);
            }
            MMA_F16_ACC(acc2[0], pa[0][0], pa[0][1], pa[0][2], pa[0][3], ONES_H2, ONES_H2);
            MMA_F16_ACC(acc2[1], pa[1][0], pa[1][1], pa[1][2], pa[1][3], ONES_H2, ONES_H2);
        }
        __syncthreads();
    }

    // Row sums came out of the ones-column MMA (cross-lane, full j range).
    const float inv0 = 1.0f/acc2[0][0], inv1 = 1.0f/acc2[0][2];
    const float inv2 = 1.0f/acc2[1][0], inv3 = 1.0f/acc2[1][2];

#pragma unroll
    for (int nb = 0; nb < 8; ++nb){
        size_t col = h*DK + nb*8 + 2*tig;
        size_t o0 = ((size_t)(b*SEQ + rowbase + g +  0))*EMB + col;
        size_t o1 = ((size_t)(b*SEQ + rowbase + g +  8))*EMB + col;
        size_t o2 = ((size_t)(b*SEQ + rowbase + g + 16))*EMB + col;
        size_t o3 = ((size_t)(b*SEQ + rowbase + g + 24))*EMB + col;
        *(float2*)&out[o0] = make_float2(acc[0][nb][0]*inv0, acc[0][nb][1]*inv0);
        *(float2*)&out[o1] = make_float2(acc[0][nb][2]*inv1, acc[0][nb][3]*inv1);
        *(float2*)&out[o2] = make_float2(acc[1][nb][0]*inv2, acc[1][nb][1]*inv2);
        *(float2*)&out[o3] = make_float2(acc[1][nb][2]*inv3, acc[1][nb][3]*inv3);
    }
}

extern "C" void kernel_launch(void* const* d_in, const int* in_sizes, int n_in,
                              void* d_out, int out_size){
    const float* x = (const float*)d_in[0];
    float* out = (float*)d_out;
    precompute_all<<<1024 + (BH*(SEQ/2)*DK)/256, 256>>>(x);
    dim3 grid(SEQ/TM, BH);
    qk_attn11<<<grid, 128>>>(out);
}